// round 14
// baseline (speedup 1.0000x reference)
#include <cuda_runtime.h>
#include <math.h>
#include <float.h>

// Problem dims
#define NV 32000
#define ND 256
#define NH 512
#define NB 16
#define NS 400
#define NT 100
#define NEX 50
#define NVX 32050   // NV + NEX
#define G4 2048     // 4*NH
#define NBLK 128    // persistent-kernel grid
#define HPAD 516    // 512+4 conflict-free float4 stride

// ---------------- scratch ----------------
__device__ float dEncWT_f[768 * G4];      // rows 0..255 WihT (D), 256..767 WhhT (H)
__device__ float dEncWT_b[768 * G4];
__device__ float dDecWT[1024 * G4];
__device__ float dWprojT[1024 * NH];
__device__ float dW2hT[1024 * NH];
__device__ float dW2cT[1024 * NH];
__device__ float dWo1T[1024 * NH];
__device__ float dWo2T[NH * ND];
__device__ float dEmbT[ND * NV];

__device__ float d_gx[2 * NB * NS * G4];  // x-part of encoder gates

__device__ float d_hf[2 * NB * NH];
__device__ float d_hb[2 * NB * NH];
__device__ float d_cf[NB * NH], d_cb[NB * NH];
__device__ float d_ys[NB * NS * 1024];
__device__ float d_enc[NB * NS * NH];
__device__ float d_dh[2 * NB * NH];
__device__ float d_dc[2 * NB * NH];
__device__ float d_ctx[NB * NH];
__device__ float d_attn[NB * NS];
__device__ float d_scores[NB * NS];
__device__ float d_pgen[NB];
__device__ float d_tmp1[NB * NH];
__device__ float d_dout[NB * ND];
__device__ float d_seqmean[NB * NH];
__device__ float d_logits[NB * NV];      // holds EXP'd logits after P6
__device__ float d_pgp[NB * 8];          // pgen partials (per j-slice)
__device__ float d_ps6[NBLK * NB];       // per-block exp-sums

// ---------------- hierarchical barrier ----------------
__device__ unsigned int g_cnt[3][8];
__device__ unsigned int g_done[3];
__device__ volatile unsigned int g_gen2[3];

__device__ __forceinline__ void abarrier2(int id, int sub, unsigned int subTarget) {
    __syncthreads();
    if (threadIdx.x == 0) {
        __threadfence();
        unsigned int gen = g_gen2[id];
        bool released = false;
        if (atomicAdd(&g_cnt[id][sub], 1u) == subTarget - 1u) {
            if (atomicAdd(&g_done[id], 1u) == 7u) {
                g_done[id] = 0;
#pragma unroll
                for (int i = 0; i < 8; i++) g_cnt[id][i] = 0;
                __threadfence();
                g_gen2[id] = gen + 1u;
                released = true;
            }
        }
        if (!released) {
            while (g_gen2[id] == gen) { __nanosleep(32); }
        }
        __threadfence();
    }
    __syncthreads();
}

// ---------------- fast math ----------------
__device__ __forceinline__ float fexp(float x) { return __expf(x); }
__device__ __forceinline__ float flog(float x) { return __logf(x); }
__device__ __forceinline__ float sigf(float x) {
    return __fdividef(1.0f, 1.0f + __expf(-x));
}
__device__ __forceinline__ float ftanh(float x) {
    float e = __expf(2.0f * x);
    return (e - 1.0f) * __fdividef(1.0f, e + 1.0f);
}

__device__ __forceinline__ float warpReduceSum(float v) {
#pragma unroll
    for (int o = 16; o > 0; o >>= 1) v += __shfl_xor_sync(0xffffffffu, v, o);
    return v;
}
__device__ __forceinline__ float warpReduceMax(float v) {
#pragma unroll
    for (int o = 16; o > 0; o >>= 1) v = fmaxf(v, __shfl_xor_sync(0xffffffffu, v, o));
    return v;
}
__device__ float blockReduceSum(float v, float* red) {
    int lane = threadIdx.x & 31, w = threadIdx.x >> 5, nw = blockDim.x >> 5;
    v = warpReduceSum(v);
    if (lane == 0) red[w] = v;
    __syncthreads();
    float r = (threadIdx.x < nw) ? red[threadIdx.x] : 0.0f;
    if (w == 0) r = warpReduceSum(r);
    if (threadIdx.x == 0) red[0] = r;
    __syncthreads();
    float res = red[0];
    __syncthreads();
    return res;
}
__device__ float blockReduceMax(float v, float* red) {
    int lane = threadIdx.x & 31, w = threadIdx.x >> 5, nw = blockDim.x >> 5;
    v = warpReduceMax(v);
    if (lane == 0) red[w] = v;
    __syncthreads();
    float r = (threadIdx.x < nw) ? red[threadIdx.x] : -FLT_MAX;
    if (w == 0) r = warpReduceMax(r);
    if (threadIdx.x == 0) red[0] = r;
    __syncthreads();
    float res = red[0];
    __syncthreads();
    return res;
}

// ---------------- transpose tile ----------------
__device__ __forceinline__ void transpose_tile(const float* __restrict__ src, int M, int N,
                                               float* __restrict__ dst, int rowOff, int stride,
                                               float (*tile)[33], int bx, int by) {
    if (bx * 32 >= N || by * 32 >= M) return;
    int tx = threadIdx.x, ty = threadIdx.y;
#pragma unroll
    for (int j = 0; j < 32; j += 8) {
        int n = bx * 32 + tx;
        int m = by * 32 + ty + j;
        if (n < N && m < M) tile[ty + j][tx] = src[(size_t)m * N + n];
    }
    __syncthreads();
#pragma unroll
    for (int j = 0; j < 32; j += 8) {
        int m2 = by * 32 + tx;
        int n2 = bx * 32 + ty + j;
        if (n2 < N && m2 < M) dst[(size_t)(rowOff + n2) * stride + m2] = tile[tx][ty + j];
    }
}

// launch 0: all weight transposes
__global__ void k_setup_w(const float* eWih_f, const float* eWhh_f,
                          const float* eWih_b, const float* eWhh_b,
                          const float* dWih, const float* dWhh,
                          const float* Wproj, const float* W2h,
                          const float* W2c, const float* Wo1, const float* Wo2) {
    __shared__ float tile[32][33];
    int bx = blockIdx.x, by = blockIdx.y;
    switch (blockIdx.z) {
        case 0:  transpose_tile(eWih_f, 2048, 256, dEncWT_f, 0,   G4, tile, bx, by); break;
        case 1:  transpose_tile(eWhh_f, 2048, 512, dEncWT_f, 256, G4, tile, bx, by); break;
        case 2:  transpose_tile(eWih_b, 2048, 256, dEncWT_b, 0,   G4, tile, bx, by); break;
        case 3:  transpose_tile(eWhh_b, 2048, 512, dEncWT_b, 256, G4, tile, bx, by); break;
        case 4:  transpose_tile(dWih,   2048, 512, dDecWT,   0,   G4, tile, bx, by); break;
        case 5:  transpose_tile(dWhh,   2048, 512, dDecWT,   512, G4, tile, bx, by); break;
        case 6:  transpose_tile(Wproj,  512, 1024, dWprojT,  0,   NH, tile, bx, by); break;
        case 7:  transpose_tile(W2h,    512, 1024, dW2hT,    0,   NH, tile, bx, by); break;
        case 8:  transpose_tile(W2c,    512, 1024, dW2cT,    0,   NH, tile, bx, by); break;
        case 9:  transpose_tile(Wo1,    512, 1024, dWo1T,    0,   NH, tile, bx, by); break;
        default: transpose_tile(Wo2,    256, 512,  dWo2T,    0,   ND, tile, bx, by); break;
    }
}

// launch 1: gx GEMM (z=0,1) + emb transpose (z=2); grid (32, 250, 3)
__global__ void k_gx_emb(const int* __restrict__ source, const float* __restrict__ emb) {
    if (blockIdx.z == 2) {
        __shared__ float tile[32][33];
        int flat = blockIdx.x + blockIdx.y * 32;
        if (flat >= 8 * 1000) return;
        transpose_tile(emb, NV, ND, dEmbT, 0, NV, tile, flat & 7, flat >> 3);
        return;
    }
    if (blockIdx.y >= 100) return;
    __shared__ float As[16][64];
    __shared__ float Bs[16][64];
    int dir = blockIdx.z;
    const float* W = dir ? dEncWT_b : dEncWT_f;
    int tid = threadIdx.x + threadIdx.y * 32;   // 256 threads as (32,8)
    int row0 = blockIdx.y * 64;
    int col0 = blockIdx.x * 64;
    int ty = tid >> 4, tx = tid & 15;
    float acc[4][4];
#pragma unroll
    for (int i = 0; i < 4; i++)
#pragma unroll
        for (int j = 0; j < 4; j++) acc[i][j] = 0.0f;

    int aRow = tid >> 2;
    int aK = (tid & 3) * 4;
    int row = row0 + aRow;
    int b = row / NS, s = row - b * NS;
    int tok = source[b * NS + s];
    for (int k0 = 0; k0 < ND; k0 += 16) {
        const float4 av = *reinterpret_cast<const float4*>(&emb[(size_t)tok * ND + k0 + aK]);
        As[aK + 0][aRow] = av.x;
        As[aK + 1][aRow] = av.y;
        As[aK + 2][aRow] = av.z;
        As[aK + 3][aRow] = av.w;
#pragma unroll
        for (int i = 0; i < 4; i++) {
            int idx = tid + i * 256;
            int r = idx >> 6, c = idx & 63;
            Bs[r][c] = W[(size_t)(k0 + r) * G4 + col0 + c];
        }
        __syncthreads();
#pragma unroll
        for (int kk = 0; kk < 16; kk++) {
            float4 ar = *reinterpret_cast<const float4*>(&As[kk][ty * 4]);
            float4 br = *reinterpret_cast<const float4*>(&Bs[kk][tx * 4]);
            float a[4] = {ar.x, ar.y, ar.z, ar.w};
            float bv[4] = {br.x, br.y, br.z, br.w};
#pragma unroll
            for (int i = 0; i < 4; i++)
#pragma unroll
                for (int j = 0; j < 4; j++) acc[i][j] += a[i] * bv[j];
        }
        __syncthreads();
    }
#pragma unroll
    for (int i = 0; i < 4; i++) {
        int r = row0 + ty * 4 + i;
#pragma unroll
        for (int j = 0; j < 4; j++) {
            int c = col0 + tx * 4 + j;
            d_gx[((size_t)dir * NB * NS + r) * G4 + c] = acc[i][j];
        }
    }
}

// launch 2: persistent encoder — coalesced GEMV, gx register prefetch, f4 staging
__global__ __launch_bounds__(256) void k_encoder(const int* __restrict__ slen,
                                                 const float* __restrict__ bf,
                                                 const float* __restrict__ bb) {
    __shared__ float hsm[16 * HPAD];
    __shared__ float gsm[512];
    const int tid = threadIdx.x, bid = blockIdx.x;
    const int dir = bid >> 6;
    const int lid = bid & 63;
    const int sub = lid & 7;
    const int j0 = lid << 3;
    float* hglob = dir ? d_hb : d_hf;
    const float* Wp = dir ? dEncWT_b : dEncWT_f;
    const float* bias = dir ? bb : bf;

    hglob[lid * 256 + tid] = 0.0f;

    const int w = tid >> 5, l = tid & 31;
    const int gq = l >> 3, jq = l & 7;
    const int colW = gq * NH + j0 + jq;
    const int j2 = tid >> 4, b2 = tid & 15;
    float creg = 0.0f;
    const int mylen = (tid < 128) ? slen[b2] : 0;
    const float* Wbase = Wp + (size_t)(256 + w * 64) * G4 + colW;

    // gx prefetch constants: reduce mapping idx = h2*256+tid -> (bq, colg)
    const int bq0 = tid >> 5, cq0 = tid & 31;
    const int colg0 = (cq0 >> 3) * NH + j0 + (cq0 & 7);
    const float* gxbase = d_gx + (size_t)dir * NB * NS * G4;
    // bias folded once
    const float biasg = bias[colg0];

    abarrier2(dir, sub, 8);

    for (int t = 0; t < NS; t++) {
        const int pos = dir ? (NS - 1 - t) : t;
        const int pbuf = (t & 1) * NB * NH;

        // prefetch this step's gx values into registers (DRAM latency hidden below)
        float gx0 = gxbase[((size_t)bq0 * NS + pos) * G4 + colg0];
        float gx1 = gxbase[((size_t)(bq0 + 8) * NS + pos) * G4 + colg0];

        // stage h (float4)
        {
            const float4* hg4 = reinterpret_cast<const float4*>(hglob + pbuf);
            for (int i = tid; i < NB * NH / 4; i += 256) {
                int b = i >> 7, k4 = i & 127;
                reinterpret_cast<float4*>(&hsm[b * HPAD])[k4] = hg4[b * 128 + k4];
            }
        }
        __syncthreads();

        float acc[16];
#pragma unroll
        for (int b = 0; b < 16; b++) acc[b] = 0.0f;
#pragma unroll 4
        for (int k4 = 0; k4 < 16; k4++) {
            int kk = w * 64 + k4 * 4;
            float w0 = Wbase[(size_t)(k4 * 4 + 0) * G4];
            float w1 = Wbase[(size_t)(k4 * 4 + 1) * G4];
            float w2 = Wbase[(size_t)(k4 * 4 + 2) * G4];
            float w3 = Wbase[(size_t)(k4 * 4 + 3) * G4];
#pragma unroll
            for (int b = 0; b < 16; b++) {
                float4 x = *reinterpret_cast<const float4*>(&hsm[b * HPAD + kk]);
                acc[b] += w0 * x.x + w1 * x.y + w2 * x.z + w3 * x.w;
            }
        }
        __syncthreads();
        float hold = (tid < 128) ? hsm[b2 * HPAD + j0 + j2] : 0.0f;
        __syncthreads();
        float* psm = hsm;
#pragma unroll
        for (int b = 0; b < 16; b++) psm[w * 512 + b * 32 + l] = acc[b];
        __syncthreads();

        // reduce + gx(reg) + bias -> gsm
        {
            float s0 = 0.0f, s1 = 0.0f;
#pragma unroll
            for (int w2 = 0; w2 < 8; w2++) {
                s0 += psm[w2 * 512 + bq0 * 32 + cq0];
                s1 += psm[w2 * 512 + (bq0 + 8) * 32 + cq0];
            }
            int gg = cq0 >> 3, jj = cq0 & 7;
            gsm[gg * 128 + jj * 16 + bq0] = s0 + biasg + gx0;
            gsm[gg * 128 + jj * 16 + bq0 + 8] = s1 + biasg + gx1;
        }
        __syncthreads();

        if (tid < 128) {
            float iv = gsm[0 + j2 * 16 + b2];
            float fv = gsm[128 + j2 * 16 + b2];
            float gg = gsm[256 + j2 * 16 + b2];
            float ov = gsm[384 + j2 * 16 + b2];
            float cn = sigf(fv) * creg + sigf(iv) * ftanh(gg);
            float hn = sigf(ov) * ftanh(cn);
            int m = pos < mylen;
            creg = m ? cn : creg;
            hglob[(pbuf ^ (NB * NH)) + b2 * NH + j0 + j2] = m ? hn : hold;
            d_ys[((size_t)b2 * NS + pos) * 1024 + dir * NH + j0 + j2] = m ? hn : 0.0f;
            if (t == NS - 1) {
                float* cg = dir ? d_cb : d_cf;
                cg[b2 * NH + j0 + j2] = creg;
            }
        }
        abarrier2(dir, sub, 8);
    }
}

// launch 3: zero-out + proj GEMM + decinit + 100-step decoder
__global__ __launch_bounds__(256) void k_megadec(
    const int* __restrict__ target, const int* __restrict__ srcext,
    const int* __restrict__ slen, const float* __restrict__ emb,
    const float* __restrict__ bproj,
    const float* __restrict__ b2h, const float* __restrict__ b2c,
    const float* __restrict__ decb, const float* __restrict__ bo1v,
    const float* __restrict__ Wpgen, const float* __restrict__ bpgen,
    float* __restrict__ out)
{
    __shared__ float SMB[8 * 1028];
    __shared__ float gsm[256];
    __shared__ float red[32];
    const int tid = threadIdx.x, bid = blockIdx.x;
    const int lane = tid & 31, warp = tid >> 5;
    const int sub = bid & 7;

    // stage A0: pre-zero entire output once
    {
        float4 z4 = make_float4(0.0f, 0.0f, 0.0f, 0.0f);
        float4* o4 = reinterpret_cast<float4*>(out);
        const size_t n4 = (size_t)NT * NB * NVX / 4;
        for (size_t i = (size_t)bid * 256 + tid; i < n4; i += (size_t)NBLK * 256)
            o4[i] = z4;
    }

    // stage A: projection GEMM (800 tiles)
    {
        float* As = SMB;
        float* Bs = SMB + 1024;
        int ty = tid >> 4, tx = tid & 15;
        int aRow = tid >> 2;
        int aK = (tid & 3) * 4;
        for (int tile = bid; tile < 800; tile += NBLK) {
            int row0 = (tile >> 3) * 64;
            int col0 = (tile & 7) * 64;
            float acc[4][4];
#pragma unroll
            for (int i = 0; i < 4; i++)
#pragma unroll
                for (int j = 0; j < 4; j++) acc[i][j] = 0.0f;
            for (int k0 = 0; k0 < 1024; k0 += 16) {
                const float4 av = *reinterpret_cast<const float4*>(
                    &d_ys[(size_t)(row0 + aRow) * 1024 + k0 + aK]);
                As[(aK + 0) * 64 + aRow] = av.x;
                As[(aK + 1) * 64 + aRow] = av.y;
                As[(aK + 2) * 64 + aRow] = av.z;
                As[(aK + 3) * 64 + aRow] = av.w;
#pragma unroll
                for (int i = 0; i < 4; i++) {
                    int idx = tid + i * 256;
                    int r = idx >> 6, c = idx & 63;
                    Bs[r * 64 + c] = dWprojT[(size_t)(k0 + r) * NH + col0 + c];
                }
                __syncthreads();
#pragma unroll
                for (int kk = 0; kk < 16; kk++) {
                    float4 ar = *reinterpret_cast<const float4*>(&As[kk * 64 + ty * 4]);
                    float4 br = *reinterpret_cast<const float4*>(&Bs[kk * 64 + tx * 4]);
                    float a[4] = {ar.x, ar.y, ar.z, ar.w};
                    float bv[4] = {br.x, br.y, br.z, br.w};
#pragma unroll
                    for (int i = 0; i < 4; i++)
#pragma unroll
                        for (int j = 0; j < 4; j++) acc[i][j] += a[i] * bv[j];
                }
                __syncthreads();
            }
#pragma unroll
            for (int i = 0; i < 4; i++) {
                int r = row0 + ty * 4 + i;
#pragma unroll
                for (int j = 0; j < 4; j++) {
                    int c = col0 + tx * 4 + j;
                    d_enc[(size_t)r * NH + c] = acc[i][j] + bproj[c];
                }
            }
        }
    }
    abarrier2(2, sub, 16);

    // stage B: decoder init
    if (bid < 32) {
        int idx = bid * 256 + tid;
        int b = idx >> 9, j = idx & 511;
        float ah = 0.0f, ac = 0.0f;
#pragma unroll 4
        for (int k = 0; k < NH; k++) {
            float hf = d_hf[b * NH + k], hbv = d_hb[b * NH + k];
            float cf = d_cf[b * NH + k], cbv = d_cb[b * NH + k];
            ah += hf * dW2hT[(size_t)k * NH + j] + hbv * dW2hT[(size_t)(k + NH) * NH + j];
            ac += cf * dW2cT[(size_t)k * NH + j] + cbv * dW2cT[(size_t)(k + NH) * NH + j];
        }
        d_dh[idx] = ah + b2h[j];
        d_dc[idx] = ac + b2c[j];
        int len = slen[b];
        float s = 0.0f;
        for (int ss = 0; ss < len; ss++) s += d_enc[((size_t)b * NS + ss) * NH + j];
        d_seqmean[idx] = __fdividef(s, (float)len);
    }
    abarrier2(2, sub, 16);
    if (bid < 32) {
        int idx = bid * 256 + tid;
        int b = idx >> 9, j = idx & 511;
        float a = 0.0f;
#pragma unroll 4
        for (int k = 0; k < NH; k++) {
            a += d_dh[b * NH + k] * dWo1T[(size_t)k * NH + j];
            a += d_seqmean[b * NH + k] * dWo1T[(size_t)(k + NH) * NH + j];
        }
        d_tmp1[idx] = ftanh(a + bo1v[j]);
    }
    abarrier2(2, sub, 16);
    if (bid < 16) {
        int idx = bid * 256 + tid;
        int b = idx >> 8, j = idx & 255;
        float a = 0.0f;
#pragma unroll 4
        for (int k = 0; k < NH; k++) a += d_tmp1[b * NH + k] * dWo2T[(size_t)k * ND + j];
        d_dout[idx] = a;
    }
    abarrier2(2, sub, 16);

    // P1 constants
    const int bg = bid >> 6, j0 = (bid & 63) << 3;
    const int gq = lane >> 3, jq = lane & 7;
    const int colW = gq * NH + j0 + jq;
    const float* WbD = dDecWT + (size_t)(warp * 128) * G4 + colW;

    // stage C: 100 decoder steps
    for (int t = 0; t < NT; t++) {
        const int pcur = (t & 1) * NB * NH;
        const int pnxt = ((t + 1) & 1) * NB * NH;
        float* outrow_base = out + (size_t)t * NB * NVX;

        // ---- P1: gates + cell ----
        {
            for (int idx = tid; idx < 8 * 1024; idx += 256) {
                int bb = idx >> 10, k = idx & 1023;
                int b = bg * 8 + bb;
                float v;
                if (k < ND) v = emb[(size_t)target[b * NT + t] * ND + k];
                else if (k < 2 * ND) v = d_dout[b * ND + k - ND];
                else v = d_dh[pcur + b * NH + k - 2 * ND];
                SMB[bb * 1028 + k] = v;
            }
            __syncthreads();
            float acc[8];
#pragma unroll
            for (int bb = 0; bb < 8; bb++) acc[bb] = 0.0f;
#pragma unroll 4
            for (int k4 = 0; k4 < 32; k4++) {
                int kk = warp * 128 + k4 * 4;
                float w0 = WbD[(size_t)(k4 * 4 + 0) * G4];
                float w1 = WbD[(size_t)(k4 * 4 + 1) * G4];
                float w2 = WbD[(size_t)(k4 * 4 + 2) * G4];
                float w3 = WbD[(size_t)(k4 * 4 + 3) * G4];
#pragma unroll
                for (int bb = 0; bb < 8; bb++) {
                    float4 x = *reinterpret_cast<const float4*>(&SMB[bb * 1028 + kk]);
                    acc[bb] += w0 * x.x + w1 * x.y + w2 * x.z + w3 * x.w;
                }
            }
            __syncthreads();
            float* psm = SMB;
#pragma unroll
            for (int bb = 0; bb < 8; bb++) psm[warp * 256 + bb * 32 + lane] = acc[bb];
            __syncthreads();
            {
                int bq = tid >> 5, cq = tid & 31;
                int gg = cq >> 3, jj = cq & 7;
                float s = 0.0f;
#pragma unroll
                for (int w2 = 0; w2 < 8; w2++) s += psm[w2 * 256 + bq * 32 + cq];
                s += decb[gg * NH + j0 + jj];
                gsm[gg * 64 + jj * 8 + bq] = s;
            }
            __syncthreads();
            if (tid < 64) {
                int jj2 = tid >> 3, b2 = tid & 7;
                int b = bg * 8 + b2, jj = j0 + jj2;
                float iv = gsm[0   + jj2 * 8 + b2];
                float fv = gsm[64  + jj2 * 8 + b2];
                float gg = gsm[128 + jj2 * 8 + b2];
                float ov = gsm[192 + jj2 * 8 + b2];
                float c = d_dc[pcur + b * NH + jj];
                float cn = sigf(fv) * c + sigf(iv) * ftanh(gg);
                float hn = sigf(ov) * ftanh(cn);
                d_dc[pnxt + b * NH + jj] = cn;
                d_dh[pnxt + b * NH + jj] = hn;
            }
        }
        abarrier2(2, sub, 16);

        // ---- P2: attention scores ----
        {
            int b = bid >> 3, s0 = (bid & 7) * 50;
            for (int i = tid; i < NH; i += 256) SMB[i] = d_dh[pnxt + b * NH + i];
            __syncthreads();
            int len = slen[b];
            for (int s = s0 + warp; s < s0 + 50; s += 8) {
                const float* er = &d_enc[((size_t)b * NS + s) * NH];
                float p = 0.0f;
#pragma unroll 4
                for (int k = lane; k < NH; k += 32) p += SMB[k] * er[k];
                p = warpReduceSum(p);
                if (lane == 0) d_scores[b * NS + s] = (s < len) ? p : -3.402823466e38f;
            }
        }
        abarrier2(2, sub, 16);

        // ---- P3: softmax (redundant, cheap) + ctx over 128 blocks + pgen partials ----
        {
            int b = bid >> 3, q8 = bid & 7, jsl = q8 * 64;
            for (int s = tid; s < NS; s += 256) SMB[s] = d_scores[b * NS + s];
            __syncthreads();
            float m = -FLT_MAX;
            for (int s = tid; s < NS; s += 256) m = fmaxf(m, SMB[s]);
            float M = blockReduceMax(m, red);
            float su = 0.0f;
            for (int s = tid; s < NS; s += 256) {
                float e = fexp(SMB[s] - M);
                SMB[s] = e;
                su += e;
            }
            float S = blockReduceSum(su, red);
            float inv = __fdividef(1.0f, S);
            if (q8 == 0) {
                for (int s = tid; s < NS; s += 256) d_attn[b * NS + s] = SMB[s] * inv;
            }
            __syncthreads();
            // ctx for this block's 64-j slice; tid = q*64 + j
            {
                int q = tid >> 6, j = tid & 63;
                int jg = jsl + j;
                const float* eb = &d_enc[(size_t)b * NS * NH + jg];
                float a = 0.0f;
#pragma unroll 8
                for (int s = q; s < NS; s += 4)
                    a += SMB[s] * eb[(size_t)s * NH];
                SMB[512 + tid] = a;
            }
            __syncthreads();
            if (tid < 64) {
                float c = (SMB[512 + tid] + SMB[576 + tid] + SMB[640 + tid] + SMB[704 + tid]) * inv;
                SMB[768 + tid] = c;
                d_ctx[b * NH + jsl + tid] = c;
            }
            __syncthreads();
            // pgen partials: ctx-slice dot; block q8==1 adds h + x parts
            float pp = 0.0f;
            if (tid < 64) pp = Wpgen[jsl + tid] * SMB[768 + tid];
            if (q8 == 1) {
                int tok = target[b * NT + t];
                for (int k = tid; k < 1024; k += 256) {
                    float cv;
                    if (k < NH) cv = d_dh[pnxt + b * NH + k];
                    else if (k < NH + ND) cv = emb[(size_t)tok * ND + k - NH];
                    else cv = d_dout[b * ND + k - NH - ND];
                    pp += Wpgen[NH + k] * cv;
                }
            }
            float ppt = blockReduceSum(pp, red);
            if (tid == 0) d_pgp[b * 8 + q8] = ppt;
        }
        abarrier2(2, sub, 16);

        // ---- P4: pgen finalize + tmp1 GEMV ----
        {
            if (bid < 16 && warp == 0) {
                float v = (lane < 8) ? d_pgp[bid * 8 + lane] : 0.0f;
                v = warpReduceSum(v);
                if (lane == 0) d_pgen[bid] = sigf(v + bpgen[0]);
            }
            int oi = bid * 64 + (tid & 63);
            int q = tid >> 6;
            int b = oi >> 9, jj = oi & 511;
            int ks = q * 256;
            float acc = 0.0f;
#pragma unroll 4
            for (int k = ks; k < ks + 256; k++) {
                float iv = (k < NH) ? d_dh[pnxt + b * NH + k] : d_ctx[b * NH + k - NH];
                acc += iv * dWo1T[(size_t)k * NH + jj];
            }
            gsm[tid] = acc;
            __syncthreads();
            if (tid < 64) {
                float s = gsm[tid] + gsm[64 + tid] + gsm[128 + tid] + gsm[192 + tid];
                d_tmp1[oi] = ftanh(s + bo1v[jj]);
            }
        }
        abarrier2(2, sub, 16);

        // ---- P5: dec_out GEMV + scatter-add (needs pgen from P4, attn from P3) ----
        {
            if (bid < 25) {
                int idx = bid * 256 + tid;  // 6400
                int b = idx / NS, s = idx - b * NS;
                float val = (1.0f - d_pgen[b]) * d_attn[b * NS + s];
                atomicAdd(outrow_base + (size_t)b * NVX + srcext[b * NS + s], val);
            }
            int oi = bid * 32 + (tid & 31);
            int q = tid >> 5;
            int b = oi >> 8, jj = oi & 255;
            int ks = q * 64;
            float acc = 0.0f;
#pragma unroll 4
            for (int k = ks; k < ks + 64; k++)
                acc += d_tmp1[b * NH + k] * dWo2T[(size_t)k * ND + jj];
            gsm[tid] = acc;
            __syncthreads();
            if (tid < 32) {
                float s = 0.0f;
#pragma unroll
                for (int q2 = 0; q2 < 8; q2++) s += gsm[q2 * 32 + tid];
                d_dout[bid * 32 + tid] = s;
            }
        }
        abarrier2(2, sub, 16);

        // ---- P6: logits GEMM -> exp (no max; |logit| << 88) + sum partials ----
        {
            for (int i = tid; i < NB * ND; i += 256) SMB[i] = d_dout[i];
            __syncthreads();
            float pv[NB];
#pragma unroll
            for (int b = 0; b < NB; b++) pv[b] = 0.0f;
            if (tid < 250) {
                int v = bid * 250 + tid;
                float acc[NB];
#pragma unroll
                for (int b = 0; b < NB; b++) acc[b] = 0.0f;
                for (int k = 0; k < ND; k += 4) {
                    float e0 = dEmbT[(size_t)(k + 0) * NV + v];
                    float e1 = dEmbT[(size_t)(k + 1) * NV + v];
                    float e2 = dEmbT[(size_t)(k + 2) * NV + v];
                    float e3 = dEmbT[(size_t)(k + 3) * NV + v];
#pragma unroll
                    for (int b = 0; b < NB; b++) {
                        const float4 dd = *reinterpret_cast<const float4*>(&SMB[b * ND + k]);
                        acc[b] += e0 * dd.x + e1 * dd.y + e2 * dd.z + e3 * dd.w;
                    }
                }
#pragma unroll
                for (int b = 0; b < NB; b++) {
                    float p = fexp(acc[b]);
                    pv[b] = p;
                    d_logits[(size_t)b * NV + v] = p;   // store exp'd
                }
            }
            __syncthreads();
#pragma unroll
            for (int b = 0; b < NB; b++) SMB[b * 256 + tid] = pv[b];
            __syncthreads();
#pragma unroll
            for (int half = 0; half < 2; half++) {
                int b = warp + half * 8;
                float s = 0.0f;
#pragma unroll
                for (int i = 0; i < 8; i++) s += SMB[b * 256 + lane + i * 32];
                s = warpReduceSum(s);
                if (lane == 0) d_ps6[bid * NB + b] = s;
            }
        }
        abarrier2(2, sub, 16);

        // ---- P7: combine sums + out = log(scale*p + residue + 1e-20) ----
        {
            int b = bid >> 3, ch = bid & 7;
            float s = (tid < NBLK) ? d_ps6[tid * NB + b] : 0.0f;
            float S = blockReduceSum(s, red);
            float scale = __fdividef(d_pgen[b], S);
            float* row = outrow_base + (size_t)b * NVX;
            int vbase = ch * 4007;
            int end = vbase + 4007; if (end > NVX) end = NVX;
            for (int v = vbase + tid; v < end; v += 256) {
                float sm = (v < NV) ? scale * d_logits[(size_t)b * NV + v] : 0.0f;
                row[v] = flog(sm + row[v] + 1e-20f);
            }
        }
        // next step's P1 barrier fences everything
    }
}

// ================================ host side ================================
extern "C" void kernel_launch(void* const* d_in, const int* in_sizes, int n_in,
                              void* d_out, int out_size) {
    const int* source   = (const int*)d_in[0];
    const int* srcext   = (const int*)d_in[1];
    const int* slen     = (const int*)d_in[2];
    const int* target   = (const int*)d_in[3];
    const float* emb    = (const float*)d_in[4];
    const float* eWih_f = (const float*)d_in[5];
    const float* eWhh_f = (const float*)d_in[6];
    const float* eb_f   = (const float*)d_in[7];
    const float* eWih_b = (const float*)d_in[8];
    const float* eWhh_b = (const float*)d_in[9];
    const float* eb_b   = (const float*)d_in[10];
    const float* Wproj  = (const float*)d_in[11];
    const float* bproj  = (const float*)d_in[12];
    const float* W2h    = (const float*)d_in[13];
    const float* b2h    = (const float*)d_in[14];
    const float* W2c    = (const float*)d_in[15];
    const float* b2c    = (const float*)d_in[16];
    const float* Wo1    = (const float*)d_in[17];
    const float* bo1    = (const float*)d_in[18];
    const float* Wo2    = (const float*)d_in[19];
    const float* dWih   = (const float*)d_in[20];
    const float* dWhh   = (const float*)d_in[21];
    const float* db     = (const float*)d_in[22];
    const float* Wpgen  = (const float*)d_in[23];
    const float* bpgen  = (const float*)d_in[24];
    float* out = (float*)d_out;

    dim3 tb(32, 8);
    k_setup_w<<<dim3(32, 64, 11), tb>>>(eWih_f, eWhh_f, eWih_b, eWhh_b,
                                        dWih, dWhh, Wproj, W2h, W2c, Wo1, Wo2);
    k_gx_emb<<<dim3(32, 250, 3), tb>>>(source, emb);
    k_encoder<<<NBLK, 256>>>(slen, eb_f, eb_b);
    k_megadec<<<NBLK, 256>>>(target, srcext, slen, emb, bproj, b2h, b2c,
                             db, bo1, Wpgen, bpgen, out);
}

// round 16
// speedup vs baseline: 1.0364x; 1.0364x over previous
#include <cuda_runtime.h>
#include <math.h>
#include <float.h>

// Problem dims
#define NV 32000
#define ND 256
#define NH 512
#define NB 16
#define NS 400
#define NT 100
#define NEX 50
#define NVX 32050   // NV + NEX
#define G4 2048     // 4*NH
#define NBLK 128    // persistent-kernel grid
#define HPAD 516    // 512+4 conflict-free float4 stride

// ---------------- scratch ----------------
__device__ float dEncWT_f[768 * G4];      // rows 0..255 WihT (D), 256..767 WhhT (H)
__device__ float dEncWT_b[768 * G4];
__device__ float dDecWT[1024 * G4];
__device__ float dWprojT[1024 * NH];
__device__ float dW2hT[1024 * NH];
__device__ float dW2cT[1024 * NH];
__device__ float dWo1T[1024 * NH];
__device__ float dWo2T[NH * ND];
__device__ float dEmbT[ND * NV];

__device__ float d_gx[2 * NB * NS * G4];  // x-part of encoder gates

__device__ float d_hf[2 * NB * NH];
__device__ float d_hb[2 * NB * NH];
__device__ float d_cf[NB * NH], d_cb[NB * NH];
__device__ float d_ys[NB * NS * 1024];
__device__ float d_enc[NB * NS * NH];
__device__ float d_dh[2 * NB * NH];
__device__ float d_dc[2 * NB * NH];
__device__ float d_ctx[NB * NH];
__device__ float d_attn[NB * NS];
__device__ float d_scores[NB * NS];
__device__ float d_pgen[NB];
__device__ float d_tmp1[NB * NH];
__device__ float d_dout[NB * ND];
__device__ float d_seqmean[NB * NH];
__device__ float d_pgp[NB * 8];          // pgen partials (per j-slice)
__device__ float d_ps6[NBLK * NB];       // per-block exp-sums

// ---------------- hierarchical barrier ----------------
__device__ unsigned int g_cnt[3][8];
__device__ unsigned int g_done[3];
__device__ volatile unsigned int g_gen2[3];

__device__ __forceinline__ void abarrier2(int id, int sub, unsigned int subTarget) {
    __syncthreads();
    if (threadIdx.x == 0) {
        __threadfence();
        unsigned int gen = g_gen2[id];
        bool released = false;
        if (atomicAdd(&g_cnt[id][sub], 1u) == subTarget - 1u) {
            if (atomicAdd(&g_done[id], 1u) == 7u) {
                g_done[id] = 0;
#pragma unroll
                for (int i = 0; i < 8; i++) g_cnt[id][i] = 0;
                __threadfence();
                g_gen2[id] = gen + 1u;
                released = true;
            }
        }
        if (!released) {
            while (g_gen2[id] == gen) { __nanosleep(32); }
        }
        __threadfence();
    }
    __syncthreads();
}

// ---------------- fast math ----------------
__device__ __forceinline__ float fexp(float x) { return __expf(x); }
__device__ __forceinline__ float flog(float x) { return __logf(x); }
__device__ __forceinline__ float sigf(float x) {
    return __fdividef(1.0f, 1.0f + __expf(-x));
}
__device__ __forceinline__ float ftanh(float x) {
    float e = __expf(2.0f * x);
    return (e - 1.0f) * __fdividef(1.0f, e + 1.0f);
}

__device__ __forceinline__ float warpReduceSum(float v) {
#pragma unroll
    for (int o = 16; o > 0; o >>= 1) v += __shfl_xor_sync(0xffffffffu, v, o);
    return v;
}
__device__ __forceinline__ float warpReduceMax(float v) {
#pragma unroll
    for (int o = 16; o > 0; o >>= 1) v = fmaxf(v, __shfl_xor_sync(0xffffffffu, v, o));
    return v;
}
__device__ float blockReduceSum(float v, float* red) {
    int lane = threadIdx.x & 31, w = threadIdx.x >> 5, nw = blockDim.x >> 5;
    v = warpReduceSum(v);
    if (lane == 0) red[w] = v;
    __syncthreads();
    float r = (threadIdx.x < nw) ? red[threadIdx.x] : 0.0f;
    if (w == 0) r = warpReduceSum(r);
    if (threadIdx.x == 0) red[0] = r;
    __syncthreads();
    float res = red[0];
    __syncthreads();
    return res;
}
__device__ float blockReduceMax(float v, float* red) {
    int lane = threadIdx.x & 31, w = threadIdx.x >> 5, nw = blockDim.x >> 5;
    v = warpReduceMax(v);
    if (lane == 0) red[w] = v;
    __syncthreads();
    float r = (threadIdx.x < nw) ? red[threadIdx.x] : -FLT_MAX;
    if (w == 0) r = warpReduceMax(r);
    if (threadIdx.x == 0) red[0] = r;
    __syncthreads();
    float res = red[0];
    __syncthreads();
    return res;
}

// ---------------- transpose tile ----------------
__device__ __forceinline__ void transpose_tile(const float* __restrict__ src, int M, int N,
                                               float* __restrict__ dst, int rowOff, int stride,
                                               float (*tile)[33], int bx, int by) {
    if (bx * 32 >= N || by * 32 >= M) return;
    int tx = threadIdx.x, ty = threadIdx.y;
#pragma unroll
    for (int j = 0; j < 32; j += 8) {
        int n = bx * 32 + tx;
        int m = by * 32 + ty + j;
        if (n < N && m < M) tile[ty + j][tx] = src[(size_t)m * N + n];
    }
    __syncthreads();
#pragma unroll
    for (int j = 0; j < 32; j += 8) {
        int m2 = by * 32 + tx;
        int n2 = bx * 32 + ty + j;
        if (n2 < N && m2 < M) dst[(size_t)(rowOff + n2) * stride + m2] = tile[tx][ty + j];
    }
}

// launch 0: all weight transposes
__global__ void k_setup_w(const float* eWih_f, const float* eWhh_f,
                          const float* eWih_b, const float* eWhh_b,
                          const float* dWih, const float* dWhh,
                          const float* Wproj, const float* W2h,
                          const float* W2c, const float* Wo1, const float* Wo2) {
    __shared__ float tile[32][33];
    int bx = blockIdx.x, by = blockIdx.y;
    switch (blockIdx.z) {
        case 0:  transpose_tile(eWih_f, 2048, 256, dEncWT_f, 0,   G4, tile, bx, by); break;
        case 1:  transpose_tile(eWhh_f, 2048, 512, dEncWT_f, 256, G4, tile, bx, by); break;
        case 2:  transpose_tile(eWih_b, 2048, 256, dEncWT_b, 0,   G4, tile, bx, by); break;
        case 3:  transpose_tile(eWhh_b, 2048, 512, dEncWT_b, 256, G4, tile, bx, by); break;
        case 4:  transpose_tile(dWih,   2048, 512, dDecWT,   0,   G4, tile, bx, by); break;
        case 5:  transpose_tile(dWhh,   2048, 512, dDecWT,   512, G4, tile, bx, by); break;
        case 6:  transpose_tile(Wproj,  512, 1024, dWprojT,  0,   NH, tile, bx, by); break;
        case 7:  transpose_tile(W2h,    512, 1024, dW2hT,    0,   NH, tile, bx, by); break;
        case 8:  transpose_tile(W2c,    512, 1024, dW2cT,    0,   NH, tile, bx, by); break;
        case 9:  transpose_tile(Wo1,    512, 1024, dWo1T,    0,   NH, tile, bx, by); break;
        default: transpose_tile(Wo2,    256, 512,  dWo2T,    0,   ND, tile, bx, by); break;
    }
}

// launch 1: gx GEMM (z=0,1) + emb transpose (z=2); grid (32, 250, 3)
__global__ void k_gx_emb(const int* __restrict__ source, const float* __restrict__ emb) {
    if (blockIdx.z == 2) {
        __shared__ float tile[32][33];
        int flat = blockIdx.x + blockIdx.y * 32;
        if (flat >= 8 * 1000) return;
        transpose_tile(emb, NV, ND, dEmbT, 0, NV, tile, flat & 7, flat >> 3);
        return;
    }
    if (blockIdx.y >= 100) return;
    __shared__ float As[16][64];
    __shared__ float Bs[16][64];
    int dir = blockIdx.z;
    const float* W = dir ? dEncWT_b : dEncWT_f;
    int tid = threadIdx.x + threadIdx.y * 32;   // 256 threads as (32,8)
    int row0 = blockIdx.y * 64;
    int col0 = blockIdx.x * 64;
    int ty = tid >> 4, tx = tid & 15;
    float acc[4][4];
#pragma unroll
    for (int i = 0; i < 4; i++)
#pragma unroll
        for (int j = 0; j < 4; j++) acc[i][j] = 0.0f;

    int aRow = tid >> 2;
    int aK = (tid & 3) * 4;
    int row = row0 + aRow;
    int b = row / NS, s = row - b * NS;
    int tok = source[b * NS + s];
    for (int k0 = 0; k0 < ND; k0 += 16) {
        const float4 av = *reinterpret_cast<const float4*>(&emb[(size_t)tok * ND + k0 + aK]);
        As[aK + 0][aRow] = av.x;
        As[aK + 1][aRow] = av.y;
        As[aK + 2][aRow] = av.z;
        As[aK + 3][aRow] = av.w;
#pragma unroll
        for (int i = 0; i < 4; i++) {
            int idx = tid + i * 256;
            int r = idx >> 6, c = idx & 63;
            Bs[r][c] = W[(size_t)(k0 + r) * G4 + col0 + c];
        }
        __syncthreads();
#pragma unroll
        for (int kk = 0; kk < 16; kk++) {
            float4 ar = *reinterpret_cast<const float4*>(&As[kk][ty * 4]);
            float4 br = *reinterpret_cast<const float4*>(&Bs[kk][tx * 4]);
            float a[4] = {ar.x, ar.y, ar.z, ar.w};
            float bv[4] = {br.x, br.y, br.z, br.w};
#pragma unroll
            for (int i = 0; i < 4; i++)
#pragma unroll
                for (int j = 0; j < 4; j++) acc[i][j] += a[i] * bv[j];
        }
        __syncthreads();
    }
#pragma unroll
    for (int i = 0; i < 4; i++) {
        int r = row0 + ty * 4 + i;
#pragma unroll
        for (int j = 0; j < 4; j++) {
            int c = col0 + tx * 4 + j;
            d_gx[((size_t)dir * NB * NS + r) * G4 + c] = acc[i][j];
        }
    }
}

// launch 2: persistent encoder — coalesced GEMV, gx register prefetch, f4 staging
__global__ __launch_bounds__(256) void k_encoder(const int* __restrict__ slen,
                                                 const float* __restrict__ bf,
                                                 const float* __restrict__ bb) {
    __shared__ float hsm[16 * HPAD];
    __shared__ float gsm[512];
    const int tid = threadIdx.x, bid = blockIdx.x;
    const int dir = bid >> 6;
    const int lid = bid & 63;
    const int sub = lid & 7;
    const int j0 = lid << 3;
    float* hglob = dir ? d_hb : d_hf;
    const float* Wp = dir ? dEncWT_b : dEncWT_f;
    const float* bias = dir ? bb : bf;

    hglob[lid * 256 + tid] = 0.0f;

    const int w = tid >> 5, l = tid & 31;
    const int gq = l >> 3, jq = l & 7;
    const int colW = gq * NH + j0 + jq;
    const int j2 = tid >> 4, b2 = tid & 15;
    float creg = 0.0f;
    const int mylen = (tid < 128) ? slen[b2] : 0;
    const float* Wbase = Wp + (size_t)(256 + w * 64) * G4 + colW;

    const int bq0 = tid >> 5, cq0 = tid & 31;
    const int colg0 = (cq0 >> 3) * NH + j0 + (cq0 & 7);
    const float* gxbase = d_gx + (size_t)dir * NB * NS * G4;
    const float biasg = bias[colg0];

    abarrier2(dir, sub, 8);

    for (int t = 0; t < NS; t++) {
        const int pos = dir ? (NS - 1 - t) : t;
        const int pbuf = (t & 1) * NB * NH;

        float gx0 = gxbase[((size_t)bq0 * NS + pos) * G4 + colg0];
        float gx1 = gxbase[((size_t)(bq0 + 8) * NS + pos) * G4 + colg0];

        {
            const float4* hg4 = reinterpret_cast<const float4*>(hglob + pbuf);
            for (int i = tid; i < NB * NH / 4; i += 256) {
                int b = i >> 7, k4 = i & 127;
                reinterpret_cast<float4*>(&hsm[b * HPAD])[k4] = hg4[b * 128 + k4];
            }
        }
        __syncthreads();

        float acc[16];
#pragma unroll
        for (int b = 0; b < 16; b++) acc[b] = 0.0f;
#pragma unroll 4
        for (int k4 = 0; k4 < 16; k4++) {
            int kk = w * 64 + k4 * 4;
            float w0 = Wbase[(size_t)(k4 * 4 + 0) * G4];
            float w1 = Wbase[(size_t)(k4 * 4 + 1) * G4];
            float w2 = Wbase[(size_t)(k4 * 4 + 2) * G4];
            float w3 = Wbase[(size_t)(k4 * 4 + 3) * G4];
#pragma unroll
            for (int b = 0; b < 16; b++) {
                float4 x = *reinterpret_cast<const float4*>(&hsm[b * HPAD + kk]);
                acc[b] += w0 * x.x + w1 * x.y + w2 * x.z + w3 * x.w;
            }
        }
        __syncthreads();
        float hold = (tid < 128) ? hsm[b2 * HPAD + j0 + j2] : 0.0f;
        __syncthreads();
        float* psm = hsm;
#pragma unroll
        for (int b = 0; b < 16; b++) psm[w * 512 + b * 32 + l] = acc[b];
        __syncthreads();

        {
            float s0 = 0.0f, s1 = 0.0f;
#pragma unroll
            for (int w2 = 0; w2 < 8; w2++) {
                s0 += psm[w2 * 512 + bq0 * 32 + cq0];
                s1 += psm[w2 * 512 + (bq0 + 8) * 32 + cq0];
            }
            int gg = cq0 >> 3, jj = cq0 & 7;
            gsm[gg * 128 + jj * 16 + bq0] = s0 + biasg + gx0;
            gsm[gg * 128 + jj * 16 + bq0 + 8] = s1 + biasg + gx1;
        }
        __syncthreads();

        if (tid < 128) {
            float iv = gsm[0 + j2 * 16 + b2];
            float fv = gsm[128 + j2 * 16 + b2];
            float gg = gsm[256 + j2 * 16 + b2];
            float ov = gsm[384 + j2 * 16 + b2];
            float cn = sigf(fv) * creg + sigf(iv) * ftanh(gg);
            float hn = sigf(ov) * ftanh(cn);
            int m = pos < mylen;
            creg = m ? cn : creg;
            hglob[(pbuf ^ (NB * NH)) + b2 * NH + j0 + j2] = m ? hn : hold;
            d_ys[((size_t)b2 * NS + pos) * 1024 + dir * NH + j0 + j2] = m ? hn : 0.0f;
            if (t == NS - 1) {
                float* cg = dir ? d_cb : d_cf;
                cg[b2 * NH + j0 + j2] = creg;
            }
        }
        abarrier2(dir, sub, 8);
    }
}

// launch 3: zero-out + proj GEMM + decinit + 100-step decoder
__global__ __launch_bounds__(256) void k_megadec(
    const int* __restrict__ target, const int* __restrict__ srcext,
    const int* __restrict__ slen, const float* __restrict__ emb,
    const float* __restrict__ bproj,
    const float* __restrict__ b2h, const float* __restrict__ b2c,
    const float* __restrict__ decb, const float* __restrict__ bo1v,
    const float* __restrict__ Wpgen, const float* __restrict__ bpgen,
    float* __restrict__ out)
{
    __shared__ float SMB[8 * 1028];   // 8224 floats: [0,4096) staging, [4096,8096) logits
    __shared__ float gsm[256];
    __shared__ float red[32];
    const int tid = threadIdx.x, bid = blockIdx.x;
    const int lane = tid & 31, warp = tid >> 5;
    const int sub = bid & 7;

    // stage A0: pre-zero entire output once
    {
        float4 z4 = make_float4(0.0f, 0.0f, 0.0f, 0.0f);
        float4* o4 = reinterpret_cast<float4*>(out);
        const size_t n4 = (size_t)NT * NB * NVX / 4;
        for (size_t i = (size_t)bid * 256 + tid; i < n4; i += (size_t)NBLK * 256)
            o4[i] = z4;
    }

    // stage A: projection GEMM (800 tiles)
    {
        float* As = SMB;
        float* Bs = SMB + 1024;
        int ty = tid >> 4, tx = tid & 15;
        int aRow = tid >> 2;
        int aK = (tid & 3) * 4;
        for (int tile = bid; tile < 800; tile += NBLK) {
            int row0 = (tile >> 3) * 64;
            int col0 = (tile & 7) * 64;
            float acc[4][4];
#pragma unroll
            for (int i = 0; i < 4; i++)
#pragma unroll
                for (int j = 0; j < 4; j++) acc[i][j] = 0.0f;
            for (int k0 = 0; k0 < 1024; k0 += 16) {
                const float4 av = *reinterpret_cast<const float4*>(
                    &d_ys[(size_t)(row0 + aRow) * 1024 + k0 + aK]);
                As[(aK + 0) * 64 + aRow] = av.x;
                As[(aK + 1) * 64 + aRow] = av.y;
                As[(aK + 2) * 64 + aRow] = av.z;
                As[(aK + 3) * 64 + aRow] = av.w;
#pragma unroll
                for (int i = 0; i < 4; i++) {
                    int idx = tid + i * 256;
                    int r = idx >> 6, c = idx & 63;
                    Bs[r * 64 + c] = dWprojT[(size_t)(k0 + r) * NH + col0 + c];
                }
                __syncthreads();
#pragma unroll
                for (int kk = 0; kk < 16; kk++) {
                    float4 ar = *reinterpret_cast<const float4*>(&As[kk * 64 + ty * 4]);
                    float4 br = *reinterpret_cast<const float4*>(&Bs[kk * 64 + tx * 4]);
                    float a[4] = {ar.x, ar.y, ar.z, ar.w};
                    float bv[4] = {br.x, br.y, br.z, br.w};
#pragma unroll
                    for (int i = 0; i < 4; i++)
#pragma unroll
                        for (int j = 0; j < 4; j++) acc[i][j] += a[i] * bv[j];
                }
                __syncthreads();
            }
#pragma unroll
            for (int i = 0; i < 4; i++) {
                int r = row0 + ty * 4 + i;
#pragma unroll
                for (int j = 0; j < 4; j++) {
                    int c = col0 + tx * 4 + j;
                    d_enc[(size_t)r * NH + c] = acc[i][j] + bproj[c];
                }
            }
        }
    }
    abarrier2(2, sub, 16);

    // stage B: decoder init
    if (bid < 32) {
        int idx = bid * 256 + tid;
        int b = idx >> 9, j = idx & 511;
        float ah = 0.0f, ac = 0.0f;
#pragma unroll 4
        for (int k = 0; k < NH; k++) {
            float hf = d_hf[b * NH + k], hbv = d_hb[b * NH + k];
            float cf = d_cf[b * NH + k], cbv = d_cb[b * NH + k];
            ah += hf * dW2hT[(size_t)k * NH + j] + hbv * dW2hT[(size_t)(k + NH) * NH + j];
            ac += cf * dW2cT[(size_t)k * NH + j] + cbv * dW2cT[(size_t)(k + NH) * NH + j];
        }
        d_dh[idx] = ah + b2h[j];
        d_dc[idx] = ac + b2c[j];
        int len = slen[b];
        float s = 0.0f;
        for (int ss = 0; ss < len; ss++) s += d_enc[((size_t)b * NS + ss) * NH + j];
        d_seqmean[idx] = __fdividef(s, (float)len);
    }
    abarrier2(2, sub, 16);
    if (bid < 32) {
        int idx = bid * 256 + tid;
        int b = idx >> 9, j = idx & 511;
        float a = 0.0f;
#pragma unroll 4
        for (int k = 0; k < NH; k++) {
            a += d_dh[b * NH + k] * dWo1T[(size_t)k * NH + j];
            a += d_seqmean[b * NH + k] * dWo1T[(size_t)(k + NH) * NH + j];
        }
        d_tmp1[idx] = ftanh(a + bo1v[j]);
    }
    abarrier2(2, sub, 16);
    if (bid < 16) {
        int idx = bid * 256 + tid;
        int b = idx >> 8, j = idx & 255;
        float a = 0.0f;
#pragma unroll 4
        for (int k = 0; k < NH; k++) a += d_tmp1[b * NH + k] * dWo2T[(size_t)k * ND + j];
        d_dout[idx] = a;
    }
    abarrier2(2, sub, 16);

    // P1 constants
    const int bg = bid >> 6, j0 = (bid & 63) << 3;
    const int gq = lane >> 3, jq = lane & 7;
    const int colW = gq * NH + j0 + jq;
    const float* WbD = dDecWT + (size_t)(warp * 128) * G4 + colW;

    // stage C: 100 decoder steps
    for (int t = 0; t < NT; t++) {
        const int pcur = (t & 1) * NB * NH;
        const int pnxt = ((t + 1) & 1) * NB * NH;
        float* outrow_base = out + (size_t)t * NB * NVX;

        // ---- P1: gates + cell ----
        {
            for (int idx = tid; idx < 8 * 1024; idx += 256) {
                int bb = idx >> 10, k = idx & 1023;
                int b = bg * 8 + bb;
                float v;
                if (k < ND) v = emb[(size_t)target[b * NT + t] * ND + k];
                else if (k < 2 * ND) v = d_dout[b * ND + k - ND];
                else v = d_dh[pcur + b * NH + k - 2 * ND];
                SMB[bb * 1028 + k] = v;
            }
            __syncthreads();
            float acc[8];
#pragma unroll
            for (int bb = 0; bb < 8; bb++) acc[bb] = 0.0f;
#pragma unroll 4
            for (int k4 = 0; k4 < 32; k4++) {
                int kk = warp * 128 + k4 * 4;
                float w0 = WbD[(size_t)(k4 * 4 + 0) * G4];
                float w1 = WbD[(size_t)(k4 * 4 + 1) * G4];
                float w2 = WbD[(size_t)(k4 * 4 + 2) * G4];
                float w3 = WbD[(size_t)(k4 * 4 + 3) * G4];
#pragma unroll
                for (int bb = 0; bb < 8; bb++) {
                    float4 x = *reinterpret_cast<const float4*>(&SMB[bb * 1028 + kk]);
                    acc[bb] += w0 * x.x + w1 * x.y + w2 * x.z + w3 * x.w;
                }
            }
            __syncthreads();
            float* psm = SMB;
#pragma unroll
            for (int bb = 0; bb < 8; bb++) psm[warp * 256 + bb * 32 + lane] = acc[bb];
            __syncthreads();
            {
                int bq = tid >> 5, cq = tid & 31;
                int gg = cq >> 3, jj = cq & 7;
                float s = 0.0f;
#pragma unroll
                for (int w2 = 0; w2 < 8; w2++) s += psm[w2 * 256 + bq * 32 + cq];
                s += decb[gg * NH + j0 + jj];
                gsm[gg * 64 + jj * 8 + bq] = s;
            }
            __syncthreads();
            if (tid < 64) {
                int jj2 = tid >> 3, b2 = tid & 7;
                int b = bg * 8 + b2, jj = j0 + jj2;
                float iv = gsm[0   + jj2 * 8 + b2];
                float fv = gsm[64  + jj2 * 8 + b2];
                float gg = gsm[128 + jj2 * 8 + b2];
                float ov = gsm[192 + jj2 * 8 + b2];
                float c = d_dc[pcur + b * NH + jj];
                float cn = sigf(fv) * c + sigf(iv) * ftanh(gg);
                float hn = sigf(ov) * ftanh(cn);
                d_dc[pnxt + b * NH + jj] = cn;
                d_dh[pnxt + b * NH + jj] = hn;
            }
        }
        abarrier2(2, sub, 16);

        // ---- P2: attention scores ----
        {
            int b = bid >> 3, s0 = (bid & 7) * 50;
            for (int i = tid; i < NH; i += 256) SMB[i] = d_dh[pnxt + b * NH + i];
            __syncthreads();
            int len = slen[b];
            for (int s = s0 + warp; s < s0 + 50; s += 8) {
                const float* er = &d_enc[((size_t)b * NS + s) * NH];
                float p = 0.0f;
#pragma unroll 4
                for (int k = lane; k < NH; k += 32) p += SMB[k] * er[k];
                p = warpReduceSum(p);
                if (lane == 0) d_scores[b * NS + s] = (s < len) ? p : -3.402823466e38f;
            }
        }
        abarrier2(2, sub, 16);

        // ---- P3: softmax (redundant, cheap) + ctx over 128 blocks + pgen partials ----
        {
            int b = bid >> 3, q8 = bid & 7, jsl = q8 * 64;
            for (int s = tid; s < NS; s += 256) SMB[s] = d_scores[b * NS + s];
            __syncthreads();
            float m = -FLT_MAX;
            for (int s = tid; s < NS; s += 256) m = fmaxf(m, SMB[s]);
            float M = blockReduceMax(m, red);
            float su = 0.0f;
            for (int s = tid; s < NS; s += 256) {
                float e = fexp(SMB[s] - M);
                SMB[s] = e;
                su += e;
            }
            float S = blockReduceSum(su, red);
            float inv = __fdividef(1.0f, S);
            if (q8 == 0) {
                for (int s = tid; s < NS; s += 256) d_attn[b * NS + s] = SMB[s] * inv;
            }
            __syncthreads();
            {
                int q = tid >> 6, j = tid & 63;
                int jg = jsl + j;
                const float* eb = &d_enc[(size_t)b * NS * NH + jg];
                float a = 0.0f;
#pragma unroll 8
                for (int s = q; s < NS; s += 4)
                    a += SMB[s] * eb[(size_t)s * NH];
                SMB[512 + tid] = a;
            }
            __syncthreads();
            if (tid < 64) {
                float c = (SMB[512 + tid] + SMB[576 + tid] + SMB[640 + tid] + SMB[704 + tid]) * inv;
                SMB[768 + tid] = c;
                d_ctx[b * NH + jsl + tid] = c;
            }
            __syncthreads();
            float pp = 0.0f;
            if (tid < 64) pp = Wpgen[jsl + tid] * SMB[768 + tid];
            if (q8 == 1) {
                int tok = target[b * NT + t];
                for (int k = tid; k < 1024; k += 256) {
                    float cv;
                    if (k < NH) cv = d_dh[pnxt + b * NH + k];
                    else if (k < NH + ND) cv = emb[(size_t)tok * ND + k - NH];
                    else cv = d_dout[b * ND + k - NH - ND];
                    pp += Wpgen[NH + k] * cv;
                }
            }
            float ppt = blockReduceSum(pp, red);
            if (tid == 0) d_pgp[b * 8 + q8] = ppt;
        }
        abarrier2(2, sub, 16);

        // ---- P4: pgen finalize + scatter (blocks 0..15) + tmp1 GEMV (all blocks) ----
        {
            if (bid < 16 && warp == 0) {
                float v = (lane < 8) ? d_pgp[bid * 8 + lane] : 0.0f;
                v = warpReduceSum(v);
                if (lane == 0) {
                    float pgv = sigf(v + bpgen[0]);
                    d_pgen[bid] = pgv;
                    red[31] = 1.0f - pgv;
                }
            }
            int oi = bid * 64 + (tid & 63);
            int q = tid >> 6;
            int b = oi >> 9, jj = oi & 511;
            int ks = q * 256;
            float acc = 0.0f;
#pragma unroll 4
            for (int k = ks; k < ks + 256; k++) {
                float iv = (k < NH) ? d_dh[pnxt + b * NH + k] : d_ctx[b * NH + k - NH];
                acc += iv * dWo1T[(size_t)k * NH + jj];
            }
            gsm[tid] = acc;
            __syncthreads();   // publishes red[31] too
            if (tid < 64) {
                float s = gsm[tid] + gsm[64 + tid] + gsm[128 + tid] + gsm[192 + tid];
                d_tmp1[oi] = ftanh(s + bo1v[jj]);
            }
            if (bid < 16) {
                float omp = red[31];
                for (int s = tid; s < NS; s += 256) {
                    float val = omp * d_attn[bid * NS + s];
                    atomicAdd(outrow_base + (size_t)bid * NVX + srcext[bid * NS + s], val);
                }
            }
        }
        abarrier2(2, sub, 16);

        // ---- P5: dec_out = tmp1 @ Wo2T ----
        {
            int oi = bid * 32 + (tid & 31);
            int q = tid >> 5;
            int b = oi >> 8, jj = oi & 255;
            int ks = q * 64;
            float acc = 0.0f;
#pragma unroll 4
            for (int k = ks; k < ks + 64; k++)
                acc += d_tmp1[b * NH + k] * dWo2T[(size_t)k * ND + jj];
            gsm[tid] = acc;
            __syncthreads();
            if (tid < 32) {
                float s = 0.0f;
#pragma unroll
                for (int q2 = 0; q2 < 8; q2++) s += gsm[q2 * 32 + tid];
                d_dout[bid * 32 + tid] = s;
            }
        }
        abarrier2(2, sub, 16);

        // ---- P6: logits GEMM -> exp kept in SMEM + per-block sum partials ----
        {
            for (int i = tid; i < NB * ND; i += 256) SMB[i] = d_dout[i];
            __syncthreads();
            float pv[NB];
#pragma unroll
            for (int b = 0; b < NB; b++) pv[b] = 0.0f;
            if (tid < 250) {
                int v = bid * 250 + tid;
                float acc[NB];
#pragma unroll
                for (int b = 0; b < NB; b++) acc[b] = 0.0f;
                for (int k = 0; k < ND; k += 4) {
                    float e0 = dEmbT[(size_t)(k + 0) * NV + v];
                    float e1 = dEmbT[(size_t)(k + 1) * NV + v];
                    float e2 = dEmbT[(size_t)(k + 2) * NV + v];
                    float e3 = dEmbT[(size_t)(k + 3) * NV + v];
#pragma unroll
                    for (int b = 0; b < NB; b++) {
                        const float4 dd = *reinterpret_cast<const float4*>(&SMB[b * ND + k]);
                        acc[b] += e0 * dd.x + e1 * dd.y + e2 * dd.z + e3 * dd.w;
                    }
                }
#pragma unroll
                for (int b = 0; b < NB; b++) {
                    float p = fexp(acc[b]);
                    pv[b] = p;
                    SMB[4096 + b * 250 + tid] = p;   // keep in smem for P7
                }
            }
            // per-warp partials -> per-block sums
#pragma unroll
            for (int b = 0; b < NB; b++) {
                float s = warpReduceSum(pv[b]);
                if (lane == 0) gsm[warp * 16 + b] = s;
            }
            __syncthreads();
            if (tid < 16) {
                float s = 0.0f;
#pragma unroll
                for (int w2 = 0; w2 < 8; w2++) s += gsm[w2 * 16 + tid];
                d_ps6[bid * NB + tid] = s;
            }
        }
        abarrier2(2, sub, 16);

        // ---- P7: all-block S reduce + fused write from SMEM logits ----
        {
            // S[b] for all 16 b: warp w handles b = 2w, 2w+1
#pragma unroll
            for (int half = 0; half < 2; half++) {
                int b = warp * 2 + half;
                float s = 0.0f;
#pragma unroll
                for (int i = 0; i < 4; i++) s += d_ps6[(lane * 4 + i) * NB + b];
                s = warpReduceSum(s);
                if (lane == 0) red[b] = s;
            }
            __syncthreads();
            if (tid < 16) red[16 + tid] = __fdividef(d_pgen[tid], red[tid]);
            __syncthreads();
            if (tid < 250) {
                int vo = bid * 250 + tid;
                float r[NB];
#pragma unroll
                for (int b = 0; b < NB; b++)
                    r[b] = outrow_base[(size_t)b * NVX + vo];
#pragma unroll
                for (int b = 0; b < NB; b++) {
                    float sm = red[16 + b] * SMB[4096 + b * 250 + tid];
                    outrow_base[(size_t)b * NVX + vo] = flog(sm + r[b] + 1e-20f);
                }
            }
            // extra tail [NV, NVX): block bid<16 handles batch b=bid with a full
            // 256-thread strided loop (FIX: previous version only used tid>=250,
            // i.e. 6 threads, leaving 44 of 50 tail entries without log)
            if (bid < 16) {
                float* row = outrow_base + (size_t)bid * NVX;
                for (int v = NV + tid; v < NVX; v += 256)
                    row[v] = flog(row[v] + 1e-20f);
            }
        }
        // next step's P1 barrier fences everything
    }
}

// ================================ host side ================================
extern "C" void kernel_launch(void* const* d_in, const int* in_sizes, int n_in,
                              void* d_out, int out_size) {
    const int* source   = (const int*)d_in[0];
    const int* srcext   = (const int*)d_in[1];
    const int* slen     = (const int*)d_in[2];
    const int* target   = (const int*)d_in[3];
    const float* emb    = (const float*)d_in[4];
    const float* eWih_f = (const float*)d_in[5];
    const float* eWhh_f = (const float*)d_in[6];
    const float* eb_f   = (const float*)d_in[7];
    const float* eWih_b = (const float*)d_in[8];
    const float* eWhh_b = (const float*)d_in[9];
    const float* eb_b   = (const float*)d_in[10];
    const float* Wproj  = (const float*)d_in[11];
    const float* bproj  = (const float*)d_in[12];
    const float* W2h    = (const float*)d_in[13];
    const float* b2h    = (const float*)d_in[14];
    const float* W2c    = (const float*)d_in[15];
    const float* b2c    = (const float*)d_in[16];
    const float* Wo1    = (const float*)d_in[17];
    const float* bo1    = (const float*)d_in[18];
    const float* Wo2    = (const float*)d_in[19];
    const float* dWih   = (const float*)d_in[20];
    const float* dWhh   = (const float*)d_in[21];
    const float* db     = (const float*)d_in[22];
    const float* Wpgen  = (const float*)d_in[23];
    const float* bpgen  = (const float*)d_in[24];
    float* out = (float*)d_out;

    dim3 tb(32, 8);
    k_setup_w<<<dim3(32, 64, 11), tb>>>(eWih_f, eWhh_f, eWih_b, eWhh_b,
                                        dWih, dWhh, Wproj, W2h, W2c, Wo1, Wo2);
    k_gx_emb<<<dim3(32, 250, 3), tb>>>(source, emb);
    k_encoder<<<NBLK, 256>>>(slen, eb_f, eb_b);
    k_megadec<<<NBLK, 256>>>(target, srcext, slen, emb, bproj, b2h, b2c,
                             db, bo1, Wpgen, bpgen, out);
}